// round 4
// baseline (speedup 1.0000x reference)
#include <cuda_runtime.h>
#include <cuda_bf16.h>

#define NUSERS 100000
#define NITEMS 200000
#define DIM    128
#define NEDGES 2000000
#define LN_EPS 1e-5f

#define NBUCKETS (NUSERS + NITEMS)          // r-buckets then c-buckets
#define SCAN_BLK 1024
#define NSCANBLK ((NBUCKETS + SCAN_BLK - 1) / SCAN_BLK)   // 293

// ---------------- scratch (device globals; no allocations allowed) ----------
__device__ __align__(16) float g_u_buf [NUSERS * DIM];   // layer-1 user out (fp32)
__device__ __align__(16) float g_i_buf [NITEMS * DIM];   // layer-1 item out (fp32)

// bf16 gather tables: row = 128 bf16 = 256B = 32 x uint2
__device__ __align__(16) uint2 g_u_bf0[NUSERS * 32];     // bf16(user_emb)
__device__ __align__(16) uint2 g_i_bf0[NITEMS * 32];     // bf16(item_emb)
__device__ __align__(16) uint2 g_u_bf1[NUSERS * 32];     // bf16(layer-1 user out)
__device__ __align__(16) uint2 g_i_bf1[NITEMS * 32];     // bf16(layer-1 item out)

// edge lists sorted by bucket key: payload = (other index, value-bits)
__device__ __align__(16) int2 g_by_r[NEDGES];            // key r, payload (c, v)
__device__ __align__(16) int2 g_by_c[NEDGES];            // key c, payload (r, v)

__device__ int g_cnt[NBUCKETS];        // histogram
__device__ int g_off[NBUCKETS + 1];    // exclusive-scan offsets (CSR), pristine
__device__ int g_cur[NBUCKETS];        // working cursors for the build scatter
__device__ int g_bsum[NSCANBLK];       // per-block sums for the scan spine

// ---------------- zero counters -----------------------------------------------
__global__ void zero_cnt_kernel() {
    int idx = blockIdx.x * blockDim.x + threadIdx.x;
    if (idx < NBUCKETS) g_cnt[idx] = 0;
}

// ---------------- histogram ---------------------------------------------------
__global__ void hist_kernel(const int* __restrict__ rows, const int* __restrict__ cols) {
    int e = blockIdx.x * blockDim.x + threadIdx.x;
    if (e >= NEDGES) return;
    atomicAdd(&g_cnt[rows[e]], 1);
    atomicAdd(&g_cnt[NUSERS + cols[e]], 1);
}

// ---------------- scan: per-block sums ----------------------------------------
__global__ void scan_bsum_kernel() {
    __shared__ int s[SCAN_BLK];
    int idx = blockIdx.x * SCAN_BLK + threadIdx.x;
    int v = (idx < NBUCKETS) ? g_cnt[idx] : 0;
    s[threadIdx.x] = v;
    __syncthreads();
    for (int o = SCAN_BLK / 2; o > 0; o >>= 1) {
        if (threadIdx.x < o) s[threadIdx.x] += s[threadIdx.x + o];
        __syncthreads();
    }
    if (threadIdx.x == 0) g_bsum[blockIdx.x] = s[0];
}

// ---------------- scan: spine (one block, parallel) ---------------------------
__global__ void scan_spine_kernel() {
    __shared__ int s[SCAN_BLK];
    int t = threadIdx.x;
    int v = (t < NSCANBLK) ? g_bsum[t] : 0;
    s[t] = v;
    __syncthreads();
    for (int o = 1; o < SCAN_BLK; o <<= 1) {
        int x = (t >= o) ? s[t - o] : 0;
        __syncthreads();
        s[t] += x;
        __syncthreads();
    }
    if (t < NSCANBLK) g_bsum[t] = s[t] - v;   // exclusive
    if (t == 0) g_off[NBUCKETS] = 2 * NEDGES;
}

// ---------------- scan: apply block-local exclusive scan ----------------------
__global__ void scan_apply_kernel() {
    __shared__ int s[SCAN_BLK];
    int idx = blockIdx.x * SCAN_BLK + threadIdx.x;
    int v = (idx < NBUCKETS) ? g_cnt[idx] : 0;
    s[threadIdx.x] = v;
    __syncthreads();
    for (int o = 1; o < SCAN_BLK; o <<= 1) {
        int t = (threadIdx.x >= o) ? s[threadIdx.x - o] : 0;
        __syncthreads();
        s[threadIdx.x] += t;
        __syncthreads();
    }
    int excl = s[threadIdx.x] - v + g_bsum[blockIdx.x];
    if (idx < NBUCKETS) {
        g_off[idx] = excl;
        g_cur[idx] = excl;
    }
}

// ---------------- build sorted edge lists -------------------------------------
__global__ void build_kernel(const int* __restrict__ rows,
                             const int* __restrict__ cols,
                             const float* __restrict__ vals) {
    int e = blockIdx.x * blockDim.x + threadIdx.x;
    if (e >= NEDGES) return;
    int r = rows[e];
    int c = cols[e];
    int vb = __float_as_int(vals[e]);
    int p1 = atomicAdd(&g_cur[r], 1);                       // in [0, NEDGES)
    g_by_r[p1] = make_int2(c, vb);
    int p2 = atomicAdd(&g_cur[NUSERS + c], 1) - NEDGES;     // in [0, NEDGES)
    g_by_c[p2] = make_int2(r, vb);
}

// ---------------- fp32 -> bf16 table conversion -------------------------------
__global__ void to_bf16_kernel(const float4* __restrict__ src,
                               uint2* __restrict__ dst, int n4) {
    int idx = blockIdx.x * blockDim.x + threadIdx.x;
    if (idx >= n4) return;
    float4 v = __ldg(&src[idx]);
    __nv_bfloat162 lo = __float22bfloat162_rn(make_float2(v.x, v.y));
    __nv_bfloat162 hi = __float22bfloat162_rn(make_float2(v.z, v.w));
    uint2 o;
    o.x = *reinterpret_cast<unsigned int*>(&lo);
    o.y = *reinterpret_cast<unsigned int*>(&hi);
    dst[idx] = o;
}

// ---------------- fused layer: gather(bf16) + residual + LN -------------------
// warp per destination row over all NUSERS+NITEMS rows.
// self/residual read fp32; messages gathered from bf16 tables; LN in-register.
template <bool WRITE_BF>
__global__ void __launch_bounds__(256) layer_kernel(
        const float4* __restrict__ self_u,   // fp32 user selves
        const float4* __restrict__ self_i,   // fp32 item selves
        const uint2*  __restrict__ bf_u,     // bf16 user gather table
        const uint2*  __restrict__ bf_i,     // bf16 item gather table
        const float*  __restrict__ gamma,
        const float*  __restrict__ beta,
        float4* __restrict__ out_u,
        float4* __restrict__ out_i,
        uint2*  __restrict__ outbf_u,
        uint2*  __restrict__ outbf_i) {
    int w    = (blockIdx.x * blockDim.x + threadIdx.x) >> 5;
    int lane = threadIdx.x & 31;
    if (w >= NUSERS + NITEMS) return;

    const float4* self4;
    const uint2*  other;
    const int2*   edges;
    float4*       out4;
    uint2*        outbf;
    int row, beg, end;
    if (w < NUSERS) {
        row   = w;
        self4 = self_u;  other = bf_i;  edges = g_by_r;
        out4  = out_u;   outbf = outbf_u;
        beg = __ldg(&g_off[row]);
        end = __ldg(&g_off[row + 1]);
    } else {
        row   = w - NUSERS;
        self4 = self_i;  other = bf_u;  edges = g_by_c;
        out4  = out_i;   outbf = outbf_i;
        beg = __ldg(&g_off[NUSERS + row])     - NEDGES;
        end = __ldg(&g_off[NUSERS + row + 1]) - NEDGES;
    }

    float4 acc = __ldg(&self4[row * 32 + lane]);   // residual (fp32)

    int p = beg;
#pragma unroll 1
    for (; p + 3 < end; p += 4) {
        int2 e0 = __ldg(&edges[p]);
        int2 e1 = __ldg(&edges[p + 1]);
        int2 e2 = __ldg(&edges[p + 2]);
        int2 e3 = __ldg(&edges[p + 3]);
        uint2 q0 = __ldg(&other[e0.x * 32 + lane]);
        uint2 q1 = __ldg(&other[e1.x * 32 + lane]);
        uint2 q2 = __ldg(&other[e2.x * 32 + lane]);
        uint2 q3 = __ldg(&other[e3.x * 32 + lane]);
        float v0 = __int_as_float(e0.y), v1 = __int_as_float(e1.y);
        float v2 = __int_as_float(e2.y), v3 = __int_as_float(e3.y);
        float2 a0 = __bfloat1622float2(*reinterpret_cast<__nv_bfloat162*>(&q0.x));
        float2 b0 = __bfloat1622float2(*reinterpret_cast<__nv_bfloat162*>(&q0.y));
        float2 a1 = __bfloat1622float2(*reinterpret_cast<__nv_bfloat162*>(&q1.x));
        float2 b1 = __bfloat1622float2(*reinterpret_cast<__nv_bfloat162*>(&q1.y));
        float2 a2 = __bfloat1622float2(*reinterpret_cast<__nv_bfloat162*>(&q2.x));
        float2 b2 = __bfloat1622float2(*reinterpret_cast<__nv_bfloat162*>(&q2.y));
        float2 a3 = __bfloat1622float2(*reinterpret_cast<__nv_bfloat162*>(&q3.x));
        float2 b3 = __bfloat1622float2(*reinterpret_cast<__nv_bfloat162*>(&q3.y));
        acc.x += v0 * a0.x + v1 * a1.x + v2 * a2.x + v3 * a3.x;
        acc.y += v0 * a0.y + v1 * a1.y + v2 * a2.y + v3 * a3.y;
        acc.z += v0 * b0.x + v1 * b1.x + v2 * b2.x + v3 * b3.x;
        acc.w += v0 * b0.y + v1 * b1.y + v2 * b2.y + v3 * b3.y;
    }
    for (; p < end; p++) {
        int2 e0 = __ldg(&edges[p]);
        uint2 q0 = __ldg(&other[e0.x * 32 + lane]);
        float v0 = __int_as_float(e0.y);
        float2 a0 = __bfloat1622float2(*reinterpret_cast<__nv_bfloat162*>(&q0.x));
        float2 b0 = __bfloat1622float2(*reinterpret_cast<__nv_bfloat162*>(&q0.y));
        acc.x += v0 * a0.x;
        acc.y += v0 * a0.y;
        acc.z += v0 * b0.x;
        acc.w += v0 * b0.y;
    }

    // LayerNorm over the 128 values held across the warp
    float s  = acc.x + acc.y + acc.z + acc.w;
    float sq = acc.x * acc.x + acc.y * acc.y + acc.z * acc.z + acc.w * acc.w;
#pragma unroll
    for (int o = 16; o > 0; o >>= 1) {
        s  += __shfl_xor_sync(0xffffffffu, s,  o);
        sq += __shfl_xor_sync(0xffffffffu, sq, o);
    }
    float m    = s * (1.f / DIM);
    float var  = sq * (1.f / DIM) - m * m;
    float rstd = rsqrtf(var + LN_EPS);

    float4 g = __ldg(&reinterpret_cast<const float4*>(gamma)[lane]);
    float4 b = __ldg(&reinterpret_cast<const float4*>(beta )[lane]);

    float4 o;
    o.x = g.x * (acc.x - m) * rstd + b.x;
    o.y = g.y * (acc.y - m) * rstd + b.y;
    o.z = g.z * (acc.z - m) * rstd + b.z;
    o.w = g.w * (acc.w - m) * rstd + b.w;
    out4[row * 32 + lane] = o;

    if (WRITE_BF) {
        __nv_bfloat162 lo = __float22bfloat162_rn(make_float2(o.x, o.y));
        __nv_bfloat162 hi = __float22bfloat162_rn(make_float2(o.z, o.w));
        uint2 ob;
        ob.x = *reinterpret_cast<unsigned int*>(&lo);
        ob.y = *reinterpret_cast<unsigned int*>(&hi);
        outbf[row * 32 + lane] = ob;
    }
}

// ---------------- launch -----------------------------------------------------
extern "C" void kernel_launch(void* const* d_in, const int* in_sizes, int n_in,
                              void* d_out, int out_size) {
    const float* user_emb = (const float*)d_in[0];
    const float* item_emb = (const float*)d_in[1];
    const float* vals     = (const float*)d_in[2];
    const float* gamma    = (const float*)d_in[3];
    const float* beta     = (const float*)d_in[4];
    const int*   rows     = (const int*)d_in[5];
    const int*   cols     = (const int*)d_in[6];

    float* out   = (float*)d_out;
    float* u_out = out;
    float* i_out = out + (size_t)NUSERS * DIM;

    void* p;
    cudaGetSymbolAddress(&p, g_u_buf);  float* u_buf = (float*)p;
    cudaGetSymbolAddress(&p, g_i_buf);  float* i_buf = (float*)p;
    cudaGetSymbolAddress(&p, g_u_bf0);  uint2* u_bf0 = (uint2*)p;
    cudaGetSymbolAddress(&p, g_i_bf0);  uint2* i_bf0 = (uint2*)p;
    cudaGetSymbolAddress(&p, g_u_bf1);  uint2* u_bf1 = (uint2*)p;
    cudaGetSymbolAddress(&p, g_i_bf1);  uint2* i_bf1 = (uint2*)p;

    const int cnt_blocks   = (NBUCKETS + 1023) / 1024;               // 293
    const int edge_blocks  = (NEDGES + 255) / 256;                   // 7813
    const int convu_blocks = (NUSERS * 32 + 255) / 256;              // 12500
    const int convi_blocks = (NITEMS * 32 + 255) / 256;              // 25000
    const int layer_blocks = ((NUSERS + NITEMS) * 32 + 255) / 256;   // 37500

    // ---- preprocessing: counting sort of edges + bf16 table conversion ----
    zero_cnt_kernel<<<cnt_blocks, 1024>>>();
    hist_kernel<<<edge_blocks, 256>>>(rows, cols);
    scan_bsum_kernel<<<NSCANBLK, SCAN_BLK>>>();
    scan_spine_kernel<<<1, SCAN_BLK>>>();
    scan_apply_kernel<<<NSCANBLK, SCAN_BLK>>>();
    build_kernel<<<edge_blocks, 256>>>(rows, cols, vals);
    to_bf16_kernel<<<convu_blocks, 256>>>((const float4*)user_emb, u_bf0, NUSERS * 32);
    to_bf16_kernel<<<convi_blocks, 256>>>((const float4*)item_emb, i_bf0, NITEMS * 32);

    // ---- layer 1: selves = originals (fp32), gathers from bf0, write buf + bf1
    layer_kernel<true><<<layer_blocks, 256>>>(
        (const float4*)user_emb, (const float4*)item_emb,
        u_bf0, i_bf0, gamma, beta,
        (float4*)u_buf, (float4*)i_buf, u_bf1, i_bf1);

    // ---- layer 2: selves = layer-1 fp32, gathers from bf1, write final out ---
    layer_kernel<false><<<layer_blocks, 256>>>(
        (const float4*)u_buf, (const float4*)i_buf,
        u_bf1, i_bf1, gamma, beta,
        (float4*)u_out, (float4*)i_out, nullptr, nullptr);
}